// round 17
// baseline (speedup 1.0000x reference)
#include <cuda_runtime.h>
#include <cuda_fp16.h>
#include <math.h>
#include <stdint.h>

// Problem constants
#define Bv      2
#define Tv      2048
#define NTOK    (Bv * Tv)      // 4096
#define Dv      512
#define Hv      8
#define HDv     64
#define FFNv    2048
#define VOCABv  256
#define Lv      2
#define CHUNK   32
#define NCHUNK  (Tv / CHUNK)   // 64
#define QKVN    1536

// weight region offsets (elements) in the fp16 weight pool ([K,N] row-major)
#define OFF_QKV 0
#define OFF_WU  (OFF_QKV + Lv * Dv * QKVN)
#define OFF_WD  (OFF_WU + Lv * Dv * FFNv)
#define OFF_WO  (OFF_WD + Lv * FFNv * Dv)
#define W_TOTAL (OFF_WO + Dv * VOCABv)

#define QKV4 (Lv * Dv * QKVN / 4)
#define WU4  (Lv * Dv * FFNv / 4)
#define WD4  (Lv * FFNv * Dv / 4)
#define WO4  (Dv * VOCABv / 4)
#define TOT4 (QKV4 + WU4 + WD4 + WO4)
#define BIA4 (Lv * QKVN / 4)
#define RFN  (Lv * Hv * HDv * HDv)
#define RF4  (RFN / 4)

// -------------------- scratch (device globals; no allocs) --------------------
__device__ float g_x[NTOK * Dv];
__device__ float g_a[NTOK * Dv];
__device__ float g_v[NTOK * Dv];
__device__ float g_qf[NTOK * Dv];
__device__ float g_kf[NTOK * Dv];
__device__ float g_S[Bv * Hv * NCHUNK * HDv * HDv];
__device__ float g_z[Bv * Hv * NCHUNK * HDv];
__device__ float g_bqkv[Lv * QKVN];
__device__ float g_part[2 * NTOK * Dv];
__device__ __half g_xh[NTOK * Dv];
__device__ __half g_xl[NTOK * Dv];
__device__ __half g_qkh[NTOK * 1024];
__device__ __half g_qkl[NTOK * 1024];
__device__ __half g_hh[NTOK * FFNv];
__device__ __half g_wh[W_TOTAL];
__device__ __half g_rfh[RFN];
__device__ __half g_rfl[RFN];

__device__ __forceinline__ void split_fp16(float v, __half& h, __half& l) {
    h = __float2half_rn(v);
    l = __float2half_rn(v - __half2float(h));
}

// -------------------- ONE fused weight conversion + bias pack + rf hi/lo ---------
__global__ void convw_all(const float* __restrict__ Wq, const float* __restrict__ Wk,
                          const float* __restrict__ Wv, const float* __restrict__ WU,
                          const float* __restrict__ WV, const float* __restrict__ Wout,
                          const float* __restrict__ bq, const float* __restrict__ bk,
                          const float* __restrict__ bvp, const float* __restrict__ rfs) {
    int idx = blockIdx.x * blockDim.x + threadIdx.x;
    if (idx < TOT4) {
        const float* src;
        int e;
        if (idx < QKV4) {
            e = idx * 4;
            int l = e / (Dv * QKVN);
            int r = e % (Dv * QKVN);
            int k = r / QKVN, col = r % QKVN;
            if (col < 512)       src = Wq + (size_t)l * Dv * Dv + k * 512 + col;
            else if (col < 1024) src = Wk + (size_t)l * Dv * Dv + k * 512 + col - 512;
            else                 src = Wv + (size_t)l * Dv * Dv + k * 512 + col - 1024;
            e += OFF_QKV;
        } else if (idx < QKV4 + WU4) {
            int e2 = (idx - QKV4) * 4;
            src = WU + e2;
            e = OFF_WU + e2;
        } else if (idx < QKV4 + WU4 + WD4) {
            int e2 = (idx - QKV4 - WU4) * 4;
            src = WV + e2;
            e = OFF_WD + e2;
        } else {
            int e2 = (idx - QKV4 - WU4 - WD4) * 4;
            src = Wout + e2;
            e = OFF_WO + e2;
        }
        float4 v = *(const float4*)src;
        ((__half2*)(g_wh + e))[0] = __half2(__float2half_rn(v.x), __float2half_rn(v.y));
        ((__half2*)(g_wh + e))[1] = __half2(__float2half_rn(v.z), __float2half_rn(v.w));
    } else if (idx < TOT4 + BIA4) {
        int j = (idx - TOT4) * 4;
#pragma unroll
        for (int q = 0; q < 4; q++) {
            int jj = j + q;
            int l = jj / QKVN, c = jj % QKVN;
            float v;
            if (c < 512) v = bq[l * Dv + c];
            else if (c < 1024) v = bk[l * Dv + c - 512];
            else v = bvp[l * Dv + c - 1024];
            g_bqkv[jj] = v;
        }
    } else if (idx < TOT4 + BIA4 + RF4) {
        int j = (idx - TOT4 - BIA4) * 4;
        float4 v = *(const float4*)(rfs + j);
        __half h0, h1, h2, h3, l0, l1, l2, l3;
        split_fp16(v.x, h0, l0); split_fp16(v.y, h1, l1);
        split_fp16(v.z, h2, l2); split_fp16(v.w, h3, l3);
        ((__half2*)(g_rfh + j))[0] = __half2(h0, h1);
        ((__half2*)(g_rfh + j))[1] = __half2(h2, h3);
        ((__half2*)(g_rfl + j))[0] = __half2(l0, l1);
        ((__half2*)(g_rfl + j))[1] = __half2(l2, l3);
    }
}

// -------------------- embedding + sinusoidal positions --------------------
__global__ void embed_kernel(const int* __restrict__ tokens,
                             const float* __restrict__ emb) {
    int idx = blockIdx.x * blockDim.x + threadIdx.x;
    if (idx >= NTOK * Dv) return;
    int n = idx >> 9;
    int j = idx & 511;
    int t = n & (Tv - 1);
    float val;
    const float c = 9.210340371976184f / 256.f;
    if (j < 256) {
        int tok = tokens[n];
        val = emb[tok * 256 + j];
    } else if (j < 384) {
        int i = j - 256;
        val = sinf((float)t * expf(-(2.f * (float)i) * c));
    } else {
        int i = j - 384;
        val = cosf((float)t * expf(-(2.f * (float)i) * c));
    }
    g_x[idx] = val;
    __half h, l;
    split_fp16(val, h, l);
    g_xh[idx] = h;
    g_xl[idx] = l;
}

// -------------------- mma helpers --------------------
__device__ __forceinline__ void ldsm_x4(uint32_t* r, const void* p) {
    uint32_t a = (uint32_t)__cvta_generic_to_shared(p);
    asm volatile("ldmatrix.sync.aligned.m8n8.x4.shared.b16 {%0,%1,%2,%3},[%4];"
        : "=r"(r[0]), "=r"(r[1]), "=r"(r[2]), "=r"(r[3]) : "r"(a));
}
__device__ __forceinline__ void ldsm_x4_t(uint32_t* r, const void* p) {
    uint32_t a = (uint32_t)__cvta_generic_to_shared(p);
    asm volatile("ldmatrix.sync.aligned.m8n8.x4.trans.shared.b16 {%0,%1,%2,%3},[%4];"
        : "=r"(r[0]), "=r"(r[1]), "=r"(r[2]), "=r"(r[3]) : "r"(a));
}
__device__ __forceinline__ void mma16816(float* c, const uint32_t* a, const uint32_t* b) {
    asm volatile("mma.sync.aligned.m16n8k16.row.col.f32.f16.f16.f32 "
        "{%0,%1,%2,%3},{%4,%5,%6,%7},{%8,%9},{%0,%1,%2,%3};"
        : "+f"(c[0]), "+f"(c[1]), "+f"(c[2]), "+f"(c[3])
        : "r"(a[0]), "r"(a[1]), "r"(a[2]), "r"(a[3]), "r"(b[0]), "r"(b[1]));
}
__device__ __forceinline__ void cp16(void* smem, const void* gmem) {
    uint32_t s = (uint32_t)__cvta_generic_to_shared(smem);
    asm volatile("cp.async.cg.shared.global [%0], [%1], 16;" :: "r"(s), "l"(gmem));
}
#define CP_COMMIT() asm volatile("cp.async.commit_group;")
#define CP_WAIT(n)  asm volatile("cp.async.wait_group %0;" :: "n"(n))

#define PADA 72
#define PADB 136
#define A_ST 18432    // one A stage: 128*72*2
#define B_ST 17408    // one B stage: 64*136*2
#define NSTG 3
#define A_TILE (NSTG * A_ST)
#define B_TILE (NSTG * B_ST)

// -------------------- tensor-core GEMM, fp16, BK=64, 3-stage cp.async ----------
// mode 0: fp32 out + bias. mode 1: gelu -> fp16 (Ch). mode 2: split-K partials.
// mode 3 (QKV): cols<1024 -> scaled fp16 hi/lo (Ch/Cl, stride 1024); cols>=1024 ->
//               fp32 (C, stride 512).
template <int TERMS>
__global__ void __launch_bounds__(256, 2)
gemm_tc(const __half* __restrict__ Ahg, const __half* __restrict__ Alg,
        const __half* __restrict__ Bhg,
        const float* __restrict__ bias, float* __restrict__ C,
        __half* __restrict__ Ch, __half* __restrict__ Cl,
        int M, int N, int lda, int ldb, int Kext, int mode) {
    extern __shared__ char smraw[];
    __half* AsH = (__half*)(smraw);
    __half* AsL = (__half*)(smraw + A_TILE);
    __half* BsH = (__half*)(smraw + (TERMS == 2 ? 2 * A_TILE : A_TILE));

    if (mode == 2) {
        size_t ko = (size_t)blockIdx.z * Kext;
        Ahg += ko;
        if (TERMS == 2) Alg += ko;
        Bhg += ko * ldb;
        C += (size_t)blockIdx.z * M * N;
    }

    int tid = threadIdx.x;
    int wid = tid >> 5, lane = tid & 31;
    int m_w = (wid >> 1) * 32, n_w = (wid & 1) * 64;
    int row0 = blockIdx.y * 128, col0 = blockIdx.x * 128;

    float acc[2][8][4];
#pragma unroll
    for (int i = 0; i < 2; i++)
#pragma unroll
        for (int j = 0; j < 8; j++)
#pragma unroll
            for (int q = 0; q < 4; q++) acc[i][j][q] = 0.f;

    int a_row = tid >> 1, a_colb = (tid & 1) * 32;
    int b_row = tid >> 2, b_colb = (tid & 3) * 32;

    auto loadStage = [&](int stage, int buf) {
        int k0 = stage * 64;
        const __half* aH = Ahg + (size_t)(row0 + a_row) * lda + k0 + a_colb;
        int sa = (buf * 128 + a_row) * PADA + a_colb;
        const __half* bH = Bhg + (size_t)(k0 + b_row) * ldb + col0 + b_colb;
        int sb = (buf * 64 + b_row) * PADB + b_colb;
#pragma unroll
        for (int i = 0; i < 4; i++) {
            cp16(AsH + sa + i * 8, aH + i * 8);
            cp16(BsH + sb + i * 8, bH + i * 8);
        }
        if (TERMS == 2) {
            const __half* aL = Alg + (size_t)(row0 + a_row) * lda + k0 + a_colb;
#pragma unroll
            for (int i = 0; i < 4; i++) cp16(AsL + sa + i * 8, aL + i * 8);
        }
        CP_COMMIT();
    };

    auto compute = [&](int buf) {
#pragma unroll
        for (int kk = 0; kk < 64; kk += 16) {
            uint32_t Ahf[2][4], Alf[2][4], Bhf[8][2];
#pragma unroll
            for (int i = 0; i < 2; i++) {
                int idx = (buf * 128 + m_w + i * 16 + (lane & 15)) * PADA + kk + (lane >> 4) * 8;
                ldsm_x4(Ahf[i], AsH + idx);
                if (TERMS == 2) ldsm_x4(Alf[i], AsL + idx);
            }
#pragma unroll
            for (int p = 0; p < 4; p++) {
                int idx = (buf * 64 + kk + (lane & 15)) * PADB + n_w + p * 16 + (lane >> 4) * 8;
                uint32_t r[4];
                ldsm_x4_t(r, BsH + idx);
                Bhf[2 * p][0] = r[0]; Bhf[2 * p][1] = r[1];
                Bhf[2 * p + 1][0] = r[2]; Bhf[2 * p + 1][1] = r[3];
            }
#pragma unroll
            for (int i = 0; i < 2; i++)
#pragma unroll
                for (int j = 0; j < 8; j++) {
                    mma16816(acc[i][j], Ahf[i], Bhf[j]);
                    if (TERMS == 2) mma16816(acc[i][j], Alf[i], Bhf[j]);
                }
        }
    };

    int nsteps = Kext >> 6;
    loadStage(0, 0);
    loadStage(1, 1);
    for (int s = 0; s < nsteps; s++) {
        if (s + 1 < nsteps) { CP_WAIT(1); } else { CP_WAIT(0); }
        __syncthreads();
        if (s + 2 < nsteps) loadStage(s + 2, (s + 2) % 3);
        compute(s % 3);
    }

    const float sc = 0.3535533905932738f;
    int g = lane >> 2, tg = lane & 3;
#pragma unroll
    for (int i = 0; i < 2; i++) {
#pragma unroll
        for (int j = 0; j < 8; j++) {
            int cc = col0 + n_w + j * 8 + tg * 2;
            float b0 = 0.f, b1 = 0.f;
            if (mode != 2) { b0 = bias[cc]; b1 = bias[cc + 1]; }
#pragma unroll
            for (int half = 0; half < 2; half++) {
                int r = row0 + m_w + i * 16 + g + half * 8;
                float v0 = acc[i][j][half * 2 + 0] + b0;
                float v1 = acc[i][j][half * 2 + 1] + b1;
                if (mode == 1) {
                    v0 = 0.5f * v0 * (1.f + erff(v0 * 0.7071067811865475f));
                    v1 = 0.5f * v1 * (1.f + erff(v1 * 0.7071067811865475f));
                    *(__half2*)(Ch + (size_t)r * N + cc) =
                        __half2(__float2half_rn(v0), __float2half_rn(v1));
                } else if (mode == 3) {
                    if (cc < 1024) {
                        float s0 = v0 * sc, s1 = v1 * sc;
                        __half h0, l0, h1, l1;
                        split_fp16(s0, h0, l0);
                        split_fp16(s1, h1, l1);
                        *(__half2*)(Ch + (size_t)r * 1024 + cc) = __half2(h0, h1);
                        *(__half2*)(Cl + (size_t)r * 1024 + cc) = __half2(l0, l1);
                    } else {
                        *(float2*)(C + (size_t)r * 512 + cc - 1024) = make_float2(v0, v1);
                    }
                } else {
                    *(float2*)(C + (size_t)r * N + cc) = make_float2(v0, v1);
                }
            }
        }
    }
}

// -------------------- generic split-K=2 reduce + bias (N = power of 2) ----------
__global__ void reduce2(const float* __restrict__ part, const float* __restrict__ bias,
                        float* __restrict__ out, int total4, int nmask) {
    int i = blockIdx.x * blockDim.x + threadIdx.x;
    if (i >= total4) return;
    float4 a = ((const float4*)part)[i];
    float4 b = ((const float4*)part)[i + total4];
    int col = (i * 4) & nmask;
    float4 o;
    o.x = a.x + b.x + bias[col + 0];
    o.y = a.y + b.y + bias[col + 1];
    o.z = a.z + b.z + bias[col + 2];
    o.w = a.w + b.w + bias[col + 3];
    ((float4*)out)[i] = o;
}

// -------------------- fused FAVOR+ features (tensor-core) + per-chunk sums -------
// grid (NTOK/32, Hv), 128 threads, ONE chunk per block. All staging via cp.async.
__global__ void __launch_bounds__(128)
favor_chunk(const __half* __restrict__ rfhp, const __half* __restrict__ rflp) {
    __shared__ __half XH[64][PADA];    // stacked xq(0-31), xk(32-63)
    __shared__ __half XL[64][PADA];
    __shared__ __half RFH[64][PADA];   // [d][m]
    __shared__ __half RFL[64][PADA];

    int tile = blockIdx.x, h = blockIdx.y;
    int b = tile >> 6, c = tile & 63;
    int bh = b * Hv + h;
    int tid = threadIdx.x;
    int wid = tid >> 5, lane = tid & 31;
    int t0 = c * CHUNK;

    const __half* rh = rfhp + (size_t)h * 4096;
    const __half* rl = rflp + (size_t)h * 4096;
    for (int i = tid; i < 512; i += 128) {
        int row = i >> 3, c8 = (i & 7) * 8;
        size_t src = (size_t)(b * Tv + t0 + (row & 31)) * 1024 +
                     ((row < 32) ? 0 : 512) + h * HDv + c8;
        cp16(&XH[row][c8], g_qkh + src);
        cp16(&XL[row][c8], g_qkl + src);
        cp16(&RFH[row][c8], rh + row * 64 + c8);
        cp16(&RFL[row][c8], rl + row * 64 + c8);
    }
    CP_COMMIT();
    CP_WAIT(0);
    __syncthreads();

    int m_w = wid * 16;
    float acc[8][4];
#pragma unroll
    for (int j = 0; j < 8; j++)
#pragma unroll
        for (int q = 0; q < 4; q++) acc[j][q] = 0.f;
#pragma unroll
    for (int k = 0; k < 4; k++) {
        int kk = k * 16;
        uint32_t AH[4], AL[4];
        int aidx = m_w + (lane & 15);
        ldsm_x4(AH, &XH[aidx][kk + (lane >> 4) * 8]);
        ldsm_x4(AL, &XL[aidx][kk + (lane >> 4) * 8]);
#pragma unroll
        for (int p = 0; p < 4; p++) {
            uint32_t BH[4], BL[4];
            int bidx = kk + (lane & 15);
            int bcol = p * 16 + (lane >> 4) * 8;
            ldsm_x4_t(BH, &RFH[bidx][bcol]);
            ldsm_x4_t(BL, &RFL[bidx][bcol]);
            mma16816(acc[2 * p], AH, BH);
            mma16816(acc[2 * p], AL, BH);
            mma16816(acc[2 * p], AH, BL);
            mma16816(acc[2 * p + 1], AH, BH + 2);
            mma16816(acc[2 * p + 1], AL, BH + 2);
            mma16816(acc[2 * p + 1], AH, BL + 2);
        }
    }

    // norms from fragments: hn[half] = 0.5 * sum_m dq^2 / 64  (rf rf^T = 64 I)
    float s20 = 0.f, s21 = 0.f;
#pragma unroll
    for (int j = 0; j < 8; j++) {
        s20 += acc[j][0] * acc[j][0] + acc[j][1] * acc[j][1];
        s21 += acc[j][2] * acc[j][2] + acc[j][3] * acc[j][3];
    }
    s20 += __shfl_xor_sync(0xffffffffu, s20, 1);
    s20 += __shfl_xor_sync(0xffffffffu, s20, 2);
    s21 += __shfl_xor_sync(0xffffffffu, s21, 1);
    s21 += __shfl_xor_sync(0xffffffffu, s21, 2);
    float hn[2] = {s20 * (1.f / 128.f), s21 * (1.f / 128.f)};
    __syncthreads();   // done with XH/XL/RFH/RFL -> safe to alias

    float (*kf_s)[68] = (float(*)[68])&XH[0][0];   // 32x68 fp32
    float (*V_s)[68]  = (float(*)[68])&RFH[0][0];

    // stage V via cp.async (overlaps exp/store below)
    for (int i = tid; i < 512; i += 128) {
        int tl = i >> 4, c4 = (i & 15) * 4;
        cp16(&V_s[tl][c4], g_v + (size_t)(b * Tv + t0 + tl) * 512 + h * HDv + c4);
    }
    CP_COMMIT();

    // exp + write qf/kf; k-warps also scatter kf into kf_s
    int g = lane >> 2, tg = lane & 3;
#pragma unroll
    for (int j = 0; j < 8; j++) {
        int col = j * 8 + tg * 2;
#pragma unroll
        for (int half = 0; half < 2; half++) {
            int row = m_w + g + half * 8;
            float v0 = expf(acc[j][half * 2 + 0] - hn[half]);
            float v1 = expf(acc[j][half * 2 + 1] - hn[half]);
            int trow = row & 31;
            size_t dst = (size_t)(b * Tv + t0 + trow) * Dv + h * HDv + col;
            if (row < 32) {
                *(float2*)(g_qf + dst) = make_float2(v0, v1);
            } else {
                *(float2*)(g_kf + dst) = make_float2(v0, v1);
                kf_s[trow][col] = v0;
                kf_s[trow][col + 1] = v1;
            }
        }
    }
    CP_WAIT(0);
    __syncthreads();

    // chunk outer-product sums: S_c[m][d] = sum_t kf[t][m] V[t][d]
    int om0 = (tid >> 3) * 4, od0 = (tid & 7) * 8;
    float sacc[4][8];
#pragma unroll
    for (int r = 0; r < 4; r++)
#pragma unroll
        for (int q = 0; q < 8; q++) sacc[r][q] = 0.f;
#pragma unroll 8
    for (int t = 0; t < 32; t++) {
        float4 km = *(const float4*)&kf_s[t][om0];
        float4 v0 = *(const float4*)&V_s[t][od0];
        float4 v1 = *(const float4*)&V_s[t][od0 + 4];
        float kr[4] = {km.x, km.y, km.z, km.w};
        float vr[8] = {v0.x, v0.y, v0.z, v0.w, v1.x, v1.y, v1.z, v1.w};
#pragma unroll
        for (int r = 0; r < 4; r++)
#pragma unroll
            for (int q = 0; q < 8; q++) sacc[r][q] += kr[r] * vr[q];
    }
    int sb = (bh * NCHUNK + c) * 4096;
#pragma unroll
    for (int r = 0; r < 4; r++) {
        *(float4*)(g_S + sb + (om0 + r) * 64 + od0) =
            make_float4(sacc[r][0], sacc[r][1], sacc[r][2], sacc[r][3]);
        *(float4*)(g_S + sb + (om0 + r) * 64 + od0 + 4) =
            make_float4(sacc[r][4], sacc[r][5], sacc[r][6], sacc[r][7]);
    }
    if (tid < 64) {
        float z = 0.f;
#pragma unroll
        for (int t = 0; t < 32; t++) z += kf_s[t][tid];
        g_z[(bh * NCHUNK + c) * 64 + tid] = z;
    }
}

// -------------------- exclusive scans over chunks (S and z fused) ---------------
__global__ void __launch_bounds__(64)
attn_scan() {
    int bh = blockIdx.x >> 6, m = blockIdx.x & 63, d = threadIdx.x;
    float v[NCHUNK];
#pragma unroll
    for (int c = 0; c < NCHUNK; c++)
        v[c] = g_S[((bh * NCHUNK + c) << 12) + m * 64 + d];
    float acc = 0.f;
#pragma unroll
    for (int c = 0; c < NCHUNK; c++) {
        g_S[((bh * NCHUNK + c) << 12) + m * 64 + d] = acc;
        acc += v[c];
    }
    if (m == 0) {
        float zv[NCHUNK];
#pragma unroll
        for (int c = 0; c < NCHUNK; c++) zv[c] = g_z[(bh * NCHUNK + c) * 64 + d];
        float za = 0.f;
#pragma unroll
        for (int c = 0; c < NCHUNK; c++) {
            g_z[(bh * NCHUNK + c) * 64 + d] = za;
            za += zv[c];
        }
    }
}

// -------------------- chunked-GEMM apply (cp.async staging) --------------------
__global__ void __launch_bounds__(128)
attn_apply() {
    int c = blockIdx.x, bh = blockIdx.y;
    int b = bh / Hv, h = bh % Hv;
    int tid = threadIdx.x;
    __shared__ float Qf[32][68], Kf[32][68], V[32][68];
    __shared__ float S0[64][68];
    __shared__ float A[32][36];
    __shared__ float z0[64], sden[32];
    int t0 = c * CHUNK;
    int sb = (bh * NCHUNK + c) * 4096;

    for (int i = tid; i < 512; i += 128) {
        int row = i >> 4, c4 = (i & 15) * 4;
        size_t qb = (size_t)(b * Tv + t0 + row) * Dv + h * HDv + c4;
        cp16(&Qf[row][c4], g_qf + qb);
        cp16(&Kf[row][c4], g_kf + qb);
        cp16(&V[row][c4], g_v + (size_t)(b * Tv + t0 + row) * 512 + h * HDv + c4);
    }
    for (int i = tid; i < 1024; i += 128) {
        int m = i >> 4, c4 = (i & 15) * 4;
        cp16(&S0[m][c4], g_S + sb + m * 64 + c4);
    }
    if (tid < 16)
        cp16(&z0[tid * 4], g_z + (bh * NCHUNK + c) * 64 + tid * 4);
    CP_COMMIT();
    CP_WAIT(0);
    __syncthreads();

    int i0 = (tid >> 4) * 4;
    int j0 = tid & 15;
    {
        float a0[4] = {0.f, 0.f, 0.f, 0.f}, a1[4] = {0.f, 0.f, 0.f, 0.f};
#pragma unroll
        for (int k = 0; k < 64; k += 4) {
            float4 ka = *(const float4*)&Kf[j0][k];
            float4 kb = *(const float4*)&Kf[j0 + 16][k];
#pragma unroll
            for (int r = 0; r < 4; r++) {
                float4 q = *(const float4*)&Qf[i0 + r][k];
                a0[r] += q.x * ka.x + q.y * ka.y + q.z * ka.z + q.w * ka.w;
                a1[r] += q.x * kb.x + q.y * kb.y + q.z * kb.z + q.w * kb.w;
            }
        }
#pragma unroll
        for (int r = 0; r < 4; r++) {
            A[i0 + r][j0] = (j0 <= i0 + r) ? a0[r] : 0.f;
            A[i0 + r][j0 + 16] = (j0 + 16 <= i0 + r) ? a1[r] : 0.f;
        }
    }
    __syncthreads();

    if (tid < 32) {
        float dn = 1e-16f;
#pragma unroll 8
        for (int m = 0; m < 64; m++) dn += Qf[tid][m] * z0[m];
#pragma unroll
        for (int j = 0; j < 32; j++) dn += A[tid][j];
        sden[tid] = dn;
    }

    int d0 = (tid & 15) * 4;
    float acc[4][4];
#pragma unroll
    for (int r = 0; r < 4; r++)
#pragma unroll
        for (int q = 0; q < 4; q++) acc[r][q] = 0.f;
#pragma unroll 4
    for (int m = 0; m < 64; m += 4) {
        float4 qv[4], sv[4];
#pragma unroll
        for (int r = 0; r < 4; r++) qv[r] = *(const float4*)&Qf[i0 + r][m];
#pragma unroll
        for (int kk = 0; kk < 4; kk++) sv[kk] = *(const float4*)&S0[m + kk][d0];
#pragma unroll
        for (int r = 0; r < 4; r++) {
            float qr[4] = {qv[r].x, qv[r].y, qv[r].z, qv[r].w};
#pragma unroll
            for (int kk = 0; kk < 4; kk++) {
                acc[r][0] += qr[kk] * sv[kk].x;
                acc[r][1] += qr[kk] * sv[kk].y;
                acc[r][2] += qr[kk] * sv[kk].z;
                acc[r][3] += qr[kk] * sv[kk].w;
            }
        }
    }
#pragma unroll 2
    for (int j = 0; j < 32; j += 4) {
        float4 av[4], vv[4];
#pragma unroll
        for (int r = 0; r < 4; r++) av[r] = *(const float4*)&A[i0 + r][j];
#pragma unroll
        for (int kk = 0; kk < 4; kk++) vv[kk] = *(const float4*)&V[j + kk][d0];
#pragma unroll
        for (int r = 0; r < 4; r++) {
            float ar[4] = {av[r].x, av[r].y, av[r].z, av[r].w};
#pragma unroll
            for (int kk = 0; kk < 4; kk++) {
                acc[r][0] += ar[kk] * vv[kk].x;
                acc[r][1] += ar[kk] * vv[kk].y;
                acc[r][2] += ar[kk] * vv[kk].z;
                acc[r][3] += ar[kk] * vv[kk].w;
            }
        }
    }
    __syncthreads();
#pragma unroll
    for (int r = 0; r < 4; r++) {
        float inv = 1.f / sden[i0 + r];
        float4 o = make_float4(acc[r][0] * inv, acc[r][1] * inv,
                               acc[r][2] * inv, acc[r][3] * inv);
        *(float4*)(g_a + (size_t)(b * Tv + t0 + i0 + r) * Dv + h * HDv + d0) = o;
    }
}

// -------------------- LayerNorm + residual add (+ fp16 hi/lo of new x) ----------
template <int RED>
__global__ void __launch_bounds__(128)
ln_add(const float* __restrict__ in0, const float* __restrict__ in1,
       const float* __restrict__ pbias,
       const float* __restrict__ g, const float* __restrict__ bl,
       float* __restrict__ x) {
    int n = blockIdx.x, tid = threadIdx.x;
    int lane = tid & 31, w = tid >> 5;
    float v[4];
    float s = 0.f, s2 = 0.f;
#pragma unroll
    for (int i = 0; i < 4; i++) {
        int j = tid + i * 128;
        float t = in0[(size_t)n * Dv + j];
        if (RED) t += in1[(size_t)n * Dv + j] + pbias[j];
        v[i] = t;
        s += t;
        s2 += t * t;
    }
    __shared__ float sh[8];
#pragma unroll
    for (int off = 16; off; off >>= 1) {
        s += __shfl_down_sync(0xffffffffu, s, off);
        s2 += __shfl_down_sync(0xffffffffu, s2, off);
    }
    if (lane == 0) { sh[w] = s; sh[4 + w] = s2; }
    __syncthreads();
    float S = sh[0] + sh[1] + sh[2] + sh[3];
    float S2 = sh[4] + sh[5] + sh[6] + sh[7];
    float mu = S * (1.f / Dv);
    float var = S2 * (1.f / Dv) - mu * mu;
    float rs = rsqrtf(var + 1e-5f);
#pragma unroll
    for (int i = 0; i < 4; i++) {
        int j = tid + i * 128;
        size_t idx = (size_t)n * Dv + j;
        float nv = x[idx] + (v[i] - mu) * rs * g[j] + bl[j];
        x[idx] = nv;
        __half h, l;
        split_fp16(nv, h, l);
        g_xh[idx] = h;
        g_xl[idx] = l;
    }
}

// -------------------- host driver --------------------
extern "C" void kernel_launch(void* const* d_in, const int* in_sizes, int n_in,
                              void* d_out, int out_size) {
    const int*   tokens = (const int*)d_in[0];
    const float* emb    = (const float*)d_in[1];
    const float* Wq     = (const float*)d_in[2];
    const float* bq     = (const float*)d_in[3];
    const float* Wk     = (const float*)d_in[4];
    const float* bk     = (const float*)d_in[5];
    const float* Wv     = (const float*)d_in[6];
    const float* bvp    = (const float*)d_in[7];
    const float* rfs    = (const float*)d_in[8];
    const float* ln1g   = (const float*)d_in[9];
    const float* ln1b   = (const float*)d_in[10];
    const float* ln2g   = (const float*)d_in[11];
    const float* ln2b   = (const float*)d_in[12];
    const float* WU     = (const float*)d_in[13];
    const float* bU     = (const float*)d_in[14];
    const float* WV     = (const float*)d_in[15];
    const float* bV     = (const float*)d_in[16];
    const float* Wout   = (const float*)d_in[17];
    const float* bout   = (const float*)d_in[18];
    float* out = (float*)d_out;

    static float *px = nullptr, *pa, *pv, *pbqkv, *ppart;
    static __half *pxh, *pxl, *pqkh, *pqkl, *phh, *pwh, *prfh, *prfl;
    if (!px) {
        cudaGetSymbolAddress((void**)&px, g_x);
        cudaGetSymbolAddress((void**)&pa, g_a);
        cudaGetSymbolAddress((void**)&pv, g_v);
        cudaGetSymbolAddress((void**)&pbqkv, g_bqkv);
        cudaGetSymbolAddress((void**)&ppart, g_part);
        cudaGetSymbolAddress((void**)&pxh, g_xh);
        cudaGetSymbolAddress((void**)&pxl, g_xl);
        cudaGetSymbolAddress((void**)&pqkh, g_qkh);
        cudaGetSymbolAddress((void**)&pqkl, g_qkl);
        cudaGetSymbolAddress((void**)&phh, g_hh);
        cudaGetSymbolAddress((void**)&pwh, g_wh);
        cudaGetSymbolAddress((void**)&prfh, g_rfh);
        cudaGetSymbolAddress((void**)&prfl, g_rfl);
        cudaFuncSetAttribute(gemm_tc<1>, cudaFuncAttributeMaxDynamicSharedMemorySize,
                             A_TILE + B_TILE);
        cudaFuncSetAttribute(gemm_tc<2>, cudaFuncAttributeMaxDynamicSharedMemorySize,
                             2 * A_TILE + B_TILE);
    }

    convw_all<<<(TOT4 + BIA4 + RF4 + 255) / 256, 256>>>(Wq, Wk, Wv, WU, WV, Wout,
                                                        bq, bk, bvp, rfs);
    embed_kernel<<<(NTOK * Dv + 255) / 256, 256>>>(tokens, emb);

    for (int l = 0; l < Lv; l++) {
        gemm_tc<1><<<dim3(QKVN / 128, NTOK / 128), 256, A_TILE + B_TILE>>>(
            pxh, nullptr, pwh + OFF_QKV + (size_t)l * Dv * QKVN, pbqkv + l * QKVN,
            pv, pqkh, pqkl, NTOK, QKVN, Dv, QKVN, Dv, 3);

        favor_chunk<<<dim3(NTOK / 32, Hv), 128>>>(prfh + (size_t)l * Hv * 4096,
                                                  prfl + (size_t)l * Hv * 4096);
        attn_scan<<<Bv * Hv * HDv, 64>>>();
        attn_apply<<<dim3(NCHUNK, Bv * Hv), 128>>>();

        ln_add<0><<<NTOK, 128>>>(pa, nullptr, nullptr,
                                 ln1g + l * Dv, ln1b + l * Dv, px);

        gemm_tc<1><<<dim3(FFNv / 128, NTOK / 128), 256, A_TILE + B_TILE>>>(
            pxh, nullptr, pwh + OFF_WU + (size_t)l * Dv * FFNv, bU + l * FFNv,
            nullptr, phh, nullptr, NTOK, FFNv, Dv, FFNv, Dv, 1);

        gemm_tc<1><<<dim3(Dv / 128, NTOK / 128, 2), 256, A_TILE + B_TILE>>>(
            phh, nullptr, pwh + OFF_WD + (size_t)l * FFNv * Dv, nullptr,
            ppart, nullptr, nullptr, NTOK, Dv, FFNv, Dv, 1024, 2);

        ln_add<1><<<NTOK, 128>>>(ppart, ppart + (size_t)NTOK * Dv, bV + l * Dv,
                                 ln2g + l * Dv, ln2b + l * Dv, px);
    }

    gemm_tc<2><<<dim3(VOCABv / 128, NTOK / 128, 2), 256, 2 * A_TILE + B_TILE>>>(
        pxh, pxl, pwh + OFF_WO, nullptr, ppart, nullptr, nullptr,
        NTOK, VOCABv, Dv, VOCABv, 256, 2);
    reduce2<<<(NTOK * VOCABv / 4 + 255) / 256, 256>>>(ppart, bout, out,
                                                      NTOK * VOCABv / 4, VOCABv - 1);
}